// round 17
// baseline (speedup 1.0000x reference)
#include <cuda_runtime.h>
#include <math.h>
#include <stdint.h>

// Problem constants
#define BB 4
#define TT 64
#define CC 512
#define HW 196          // 14*14 spatial positions
#define BN (BB*HW)      // 784
#define NROWS (BN*TT)   // 50176
#define NH 8
#define DH 64
#define KTOP 19         // int(0.3*64)
#define ALPHA 0.2f
// DistanceAdj band: reference's Eigen pexp flushes subnormal outputs ->
// adj0=exp(-(0.6d^2+0.2)) > 0 iff |d| <= 12. (verified)
#define DBAND 12

// -------- device global scratch --------
__device__ float g_xr[(size_t)NROWS * CC];          // [BN,T,C]
__device__ float g_y [(size_t)NROWS * CC];          // pre-LN result
__device__ float2 g_stats[NROWS];                   // (mu, rstd)
__device__ unsigned long long g_sel[BN];            // top-k union mask bits
__device__ float g_magp[(size_t)NROWS * 16];        // per-row sumsq partials
__device__ float2 g_lnp[(size_t)NROWS * 4];         // per-row (sum,sumsq) partials

// -------- helpers --------
__device__ __forceinline__ void mma_tf32(float c[4], const uint32_t a[4], const uint32_t b[2]) {
    asm volatile(
        "mma.sync.aligned.m16n8k8.row.col.f32.tf32.tf32.f32 "
        "{%0,%1,%2,%3}, {%4,%5,%6,%7}, {%8,%9}, {%0,%1,%2,%3};"
        : "+f"(c[0]), "+f"(c[1]), "+f"(c[2]), "+f"(c[3])
        : "r"(a[0]), "r"(a[1]), "r"(a[2]), "r"(a[3]), "r"(b[0]), "r"(b[1]));
}
__device__ __forceinline__ void cp_async16(uint32_t saddr, const void* g) {
    asm volatile("cp.async.cg.shared.global [%0], [%1], 16;" :: "r"(saddr), "l"(g));
}
#define CP_COMMIT() asm volatile("cp.async.commit_group;")
#define CP_WAIT1()  asm volatile("cp.async.wait_group 1;")
#define CP_WAIT0()  asm volatile("cp.async.wait_group 0;")

// -------- kernel 1: transpose x -> xr, emitting sumsq partials --------
__global__ void transpose_in_kernel(const float* __restrict__ x) {
    __shared__ float tile[32][33];
    __shared__ float red[8][33];
    int bt = blockIdx.z;                  // b*64+t
    int n0 = blockIdx.x * 32;
    int c0 = blockIdx.y * 32;
    int tx = threadIdx.x, ty = threadIdx.y;
    int b = bt >> 6, t = bt & 63;
    float part = 0.f;
#pragma unroll
    for (int i = 0; i < 4; i++) {
        int cl = ty + i * 8;
        int n = n0 + tx;
        if (n < HW) {
            float v = x[((size_t)bt * CC + (c0 + cl)) * HW + n];
            tile[cl][tx] = v;
            part = fmaf(v, v, part);
        }
    }
    red[ty][tx] = part;
    __syncthreads();
#pragma unroll
    for (int i = 0; i < 4; i++) {
        int nl = ty + i * 8;
        int n = n0 + nl;
        if (n < HW)
            g_xr[(((size_t)(b * HW + n)) * TT + t) * CC + c0 + tx] = tile[tx][nl];
    }
    if (ty == 0) {
        int n = n0 + tx;
        if (n < HW) {
            float s = 0.f;
#pragma unroll
            for (int r = 0; r < 8; r++) s += red[r][tx];
            g_magp[(((size_t)(b * HW + n)) * TT + t) * 16 + blockIdx.y] = s;
        }
    }
}

// -------- kernel 2: per-bn top-k mask from sumsq partials --------
__global__ void sel2_kernel() {
    __shared__ float m2[64];
    __shared__ unsigned long long mparts[2];
    const int bn = blockIdx.x;
    const int tid = threadIdx.x;   // 0..63
    {
        const float* p = g_magp + ((size_t)bn * TT + tid) * 16;
        float s = 0.f;
#pragma unroll
        for (int i = 0; i < 16; i++) s += p[i];
        m2[tid] = s;               // sumsq; sqrt monotone -> same ranks
    }
    __syncthreads();
    float m = m2[tid];
    int rank = 0;
#pragma unroll 8
    for (int s = 0; s < 64; s++) {
        float ms = m2[s];
        rank += (ms > m) || (ms == m && s < tid);
    }
    unsigned bal = __ballot_sync(~0u, rank < KTOP);
    if ((tid & 31) == 0) mparts[tid >> 5] = bal;
    __syncthreads();
    if (tid == 0) g_sel[bn] = mparts[0] | (mparts[1] << 32);
}

// ===== fused GAT: 2 bn x 2 heads per block (512 thr), tf32 mma + cp.async ====
// grid (392, 4): blockIdx.y = head-pair hp (heads 2hp, 2hp+1)
// smem floats: hh[128][132] (16896) | stg 17920 { phase1: As[2][128][36](9216)
//              + Bs[2][32][136](8704); phase2: att[128][132](16896) }
//              | f1p[256] f2p[256] sa1[128] sa2[128] colp[16][64](1024)
#define GAT_SMEM ((16896 + 17920 + 256 + 256 + 128 + 128 + 1024) * 4)

__global__ __launch_bounds__(512) void gat_fused_kernel(
    const float* __restrict__ Wg, const float* __restrict__ a1g,
    const float* __restrict__ a2g, float* __restrict__ tmp_out) {
    extern __shared__ float smf[];
    float* hh  = smf;                    // [128][132]
    float* stg = smf + 16896;
    float* att = stg;                    // [128][132] (phase 2)
    float* f1p  = stg + 17920;           // [2][128] logits; later inv norms [4][64]
    float* f2p  = f1p + 256;             // [2][128]
    float* sa1  = f2p + 256;             // [2][64]
    float* sa2  = sa1 + 128;             // [2][64]
    float* colp = sa2 + 128;             // [16][64]
    __shared__ unsigned long long smask[2];

    const int tid = threadIdx.x;
    const int m0 = blockIdx.x * 128;
    const int hp = blockIdx.y;           // head pair
    const int bn0 = blockIdx.x * 2;
    const int lane = tid & 31, warp = tid >> 5;
    const int gid = lane >> 2, tq = lane & 3;

    if (tid < 128)       sa1[tid]       = a1g[hp * 128 + tid];
    else if (tid < 256)  sa2[tid - 128] = a2g[hp * 128 + (tid - 128)];
    else if (tid == 256) smask[0] = g_sel[bn0];
    else if (tid == 257) smask[1] = g_sel[bn0 + 1];

    // ---- phase 1: h-GEMM 128x128 (2 heads), cp.async double-buffered ----
    const int wm = (warp >> 2) * 32, wn = (warp & 3) * 32;
    const uint32_t sStg = (uint32_t)__cvta_generic_to_shared(stg);

    auto stage = [&](int k0, int s) {
#pragma unroll
        for (int i = 0; i < 2; i++) {
            int idx = tid + i * 512;
            int r = idx >> 3, c4 = (idx & 7) * 4;
            cp_async16(sStg + ((s * 4608 + r * 36 + c4) << 2),
                       &g_xr[(size_t)(m0 + r) * CC + k0 + c4]);
        }
#pragma unroll
        for (int i = 0; i < 2; i++) {
            int idx = tid + i * 512;
            int r = idx >> 5, c4 = idx & 31;
            int head = 2 * hp + (c4 >> 4);
            int d4 = (c4 & 15) * 4;
            cp_async16(sStg + ((9216 + s * 4352 + r * 136 + c4 * 4) << 2),
                       &Wg[((size_t)head * CC + (k0 + r)) * DH + d4]);
        }
        CP_COMMIT();
    };

    float acc[2][4][4] = {};
    stage(0, 0);
    for (int it = 0; it < 16; it++) {
        if (it + 1 < 16) { stage((it + 1) * 32, (it + 1) & 1); CP_WAIT1(); }
        else CP_WAIT0();
        __syncthreads();
        const float* As = stg + (it & 1) * 4608;           // [128][36]
        const float* Bs = stg + 9216 + (it & 1) * 4352;    // [32][136]
#pragma unroll
        for (int ks = 0; ks < 4; ks++) {
            const int k = ks * 8;
            uint32_t af[2][4];
#pragma unroll
            for (int mi = 0; mi < 2; mi++) {
                int base = wm + mi * 16;
                af[mi][0] = __float_as_uint(As[(base + gid) * 36 + k + tq]);
                af[mi][1] = __float_as_uint(As[(base + gid + 8) * 36 + k + tq]);
                af[mi][2] = __float_as_uint(As[(base + gid) * 36 + k + tq + 4]);
                af[mi][3] = __float_as_uint(As[(base + gid + 8) * 36 + k + tq + 4]);
            }
            uint32_t bf[4][2];
#pragma unroll
            for (int ni = 0; ni < 4; ni++) {
                int n = wn + ni * 8 + gid;
                bf[ni][0] = __float_as_uint(Bs[(k + tq) * 136 + n]);
                bf[ni][1] = __float_as_uint(Bs[(k + tq + 4) * 136 + n]);
            }
#pragma unroll
            for (int mi = 0; mi < 2; mi++)
#pragma unroll
                for (int ni = 0; ni < 4; ni++)
                    mma_tf32(acc[mi][ni], af[mi], bf[ni]);
        }
        __syncthreads();
    }
    // store h tile -> hh [128][132]
#pragma unroll
    for (int mi = 0; mi < 2; mi++)
#pragma unroll
        for (int ni = 0; ni < 4; ni++) {
            int r0 = wm + mi * 16 + gid;
            int c0 = wn + ni * 8 + tq * 2;
            float* c = acc[mi][ni];
            hh[r0 * 132 + c0]           = c[0];
            hh[r0 * 132 + c0 + 1]       = c[1];
            hh[(r0 + 8) * 132 + c0]     = c[2];
            hh[(r0 + 8) * 132 + c0 + 1] = c[3];
        }
    __syncthreads();

    // ---- phase 2: attention, four 64x64 tiles (half=bn, hd=head) ----
    {
        int which = tid >> 8;            // 0: f1, 1: f2
        int hd = (tid >> 7) & 1;
        int row = tid & 127;
        const float* w = (which ? sa2 : sa1) + hd * 64;
        const float* hr = hh + row * 132 + hd * 64;
        float s = 0.f;
#pragma unroll 16
        for (int d = 0; d < 64; d++) s = fmaf(hr[d], w[d], s);
        (which ? f2p : f1p)[hd * 128 + row] = s;
    }
    __syncthreads();

    const int ti = warp >> 2;            // tile 0..3
    const int half = ti >> 1, hd = ti & 1, wl = warp & 3;
    const unsigned long long selm = smask[half];
    for (int t = wl; t < 64; t += 4) {
        unsigned long long band = (t >= DBAND) ? (0x1FFFFFFull << (t - DBAND))
                                               : (0x1FFFFFFull >> (DBAND - t));
        unsigned long long rowm = ((((selm >> t) & 1ull) ? ~0ull : selm)) & band;
        float ft = f1p[hd * 128 + half * 64 + t];
        int s0 = lane, s1 = lane + 32;
        float e0 = ft + f2p[hd * 128 + half * 64 + s0];
        float e1 = ft + f2p[hd * 128 + half * 64 + s1];
        e0 = fmaxf(e0, ALPHA * e0);
        e1 = fmaxf(e1, ALPHA * e1);
        float l0 = ((rowm >> s0) & 1ull) ? e0 : -9e15f;
        float l1 = ((rowm >> s1) & 1ull) ? e1 : -9e15f;
        float mx = fmaxf(l0, l1);
#pragma unroll
        for (int o = 16; o; o >>= 1) mx = fmaxf(mx, __shfl_xor_sync(~0u, mx, o));
        float p0 = __expf(l0 - mx), p1 = __expf(l1 - mx);
        float sumv = p0 + p1;
#pragma unroll
        for (int o = 16; o; o >>= 1) sumv += __shfl_xor_sync(~0u, sumv, o);
        float inv = 1.f / sumv;
        att[(half * 64 + t) * 132 + hd * 64 + s0] = p0 * inv;
        att[(half * 64 + t) * 132 + hd * 64 + s1] = p1 * inv;
    }
    __syncthreads();

    // D = att @ hh per tile (4 warps/tile, acc2[8][4])
    const int rbase = half * 64, cb = hd * 64;
    float acc2[8][4] = {};
#pragma unroll
    for (int k0 = 0; k0 < 64; k0 += 8) {
        uint32_t af[4];
        af[0] = __float_as_uint(att[(rbase + wl * 16 + gid) * 132 + cb + k0 + tq]);
        af[1] = __float_as_uint(att[(rbase + wl * 16 + gid + 8) * 132 + cb + k0 + tq]);
        af[2] = __float_as_uint(att[(rbase + wl * 16 + gid) * 132 + cb + k0 + tq + 4]);
        af[3] = __float_as_uint(att[(rbase + wl * 16 + gid + 8) * 132 + cb + k0 + tq + 4]);
#pragma unroll
        for (int ni = 0; ni < 8; ni++) {
            int n = cb + ni * 8 + gid;
            uint32_t bf[2];
            bf[0] = __float_as_uint(hh[(rbase + k0 + tq) * 132 + n]);
            bf[1] = __float_as_uint(hh[(rbase + k0 + tq + 4) * 132 + n]);
            mma_tf32(acc2[ni], af, bf);
        }
    }
    __syncthreads();   // all att/hh reads done; reuse hh for sv

    float cpart[16] = {};
#pragma unroll
    for (int ni = 0; ni < 8; ni++) {
        int r0 = rbase + wl * 16 + gid;
        int c0 = cb + ni * 8 + tq * 2;
        float* c = acc2[ni];
#pragma unroll
        for (int q = 0; q < 4; q++) {
            int r = r0 + (q >> 1) * 8, cc = c0 + (q & 1);
            float v = c[q];
            float e = v > 0.f ? v : (__expf(v) - 1.f);
            float ae = fabsf(e);
            hh[r * 132 + cc] = copysignf(sqrtf(ae), e);
            cpart[ni * 2 + (q & 1)] += ae;
        }
    }
#pragma unroll
    for (int o = 4; o <= 16; o <<= 1)
#pragma unroll
        for (int j = 0; j < 16; j++)
            cpart[j] += __shfl_xor_sync(~0u, cpart[j], o);
    if (gid == 0) {
#pragma unroll
        for (int ni = 0; ni < 8; ni++) {
            colp[warp * 64 + ni * 8 + tq * 2]     = cpart[ni * 2];
            colp[warp * 64 + ni * 8 + tq * 2 + 1] = cpart[ni * 2 + 1];
        }
    }
    __syncthreads();
    if (tid < 256) {   // inverse column norms -> f1p[4][64] (logits dead)
        int t2 = tid >> 6, c = tid & 63;
        float tot = colp[(t2 * 4 + 0) * 64 + c] + colp[(t2 * 4 + 1) * 64 + c]
                  + colp[(t2 * 4 + 2) * 64 + c] + colp[(t2 * 4 + 3) * 64 + c];
        f1p[tid] = 1.f / fmaxf(sqrtf(tot), 1e-12f);
    }
    __syncthreads();

    // scale + write tmp: 128 rows x 128 cols -> CC offset hp*128 + c (contig!)
#pragma unroll
    for (int i = 0; i < 8; i++) {
        int r = (tid >> 5) + i * 16;
        int c4 = (tid & 31) * 4;
        int t3 = (r >> 6) * 2 + (c4 >> 6);          // tile index
        const float* invp = f1p + t3 * 64 + (c4 & 63);
        const float* svp = hh + r * 132 + c4;
        float4 o4 = make_float4(svp[0] * invp[0], svp[1] * invp[1],
                                svp[2] * invp[2], svp[3] * invp[3]);
        int bn = bn0 + (r >> 6), t = r & 63;
        *reinterpret_cast<float4*>(
            &tmp_out[((size_t)bn * TT + t) * CC + hp * 128 + c4]) = o4;
    }
}

// -------- gemm1: 128x128 tiles, g_y = tmp @ W2 + b2 + g_xr, LN partials ----
// grid (392, 4); block 256; dyn smem: As[2][128][36] + Bs[2][32][136]
#define GEMM1_SMEM ((9216 + 8704) * 4)
__global__ __launch_bounds__(256) void gemm_out_kernel(
    const float* __restrict__ Atmp, const float* __restrict__ Bsrc,
    const float* __restrict__ bias) {
    extern __shared__ float smg[];
    __shared__ float lsum[128][2], lsq[128][2];
    const int tid = threadIdx.x;
    const int m0 = blockIdx.x * 128;
    const int nt = blockIdx.y;
    const float* __restrict__ Bp = Bsrc + nt * 128;

    const int lane = tid & 31, warp = tid >> 5;
    const int gid = lane >> 2, tq = lane & 3;
    const int wm = (warp >> 1) * 32, wn = (warp & 1) * 64;
    const int sar = tid >> 3, sac = (tid & 7) * 4;
    const uint32_t sStg = (uint32_t)__cvta_generic_to_shared(smg);

    auto stage = [&](int k0, int s) {
#pragma unroll
        for (int i = 0; i < 4; i++) {
            int r = sar + i * 32;
            cp_async16(sStg + ((s * 4608 + r * 36 + sac) << 2),
                       &Atmp[(size_t)(m0 + r) * CC + k0 + sac]);
        }
#pragma unroll
        for (int i = 0; i < 4; i++) {
            int idx = tid + i * 256;
            int r = idx >> 5, c4 = (idx & 31) * 4;
            cp_async16(sStg + ((9216 + s * 4352 + r * 136 + c4) << 2),
                       &Bp[(size_t)(k0 + r) * CC + c4]);
        }
        CP_COMMIT();
    };

    float acc[2][8][4] = {};
    stage(0, 0);
    for (int it = 0; it < 16; it++) {
        if (it + 1 < 16) { stage((it + 1) * 32, (it + 1) & 1); CP_WAIT1(); }
        else CP_WAIT0();
        __syncthreads();
        const float* As = smg + (it & 1) * 4608;
        const float* Bs = smg + 9216 + (it & 1) * 4352;
#pragma unroll
        for (int ks = 0; ks < 4; ks++) {
            const int k = ks * 8;
            uint32_t af[2][4];
#pragma unroll
            for (int mi = 0; mi < 2; mi++) {
                int base = wm + mi * 16;
                af[mi][0] = __float_as_uint(As[(base + gid) * 36 + k + tq]);
                af[mi][1] = __float_as_uint(As[(base + gid + 8) * 36 + k + tq]);
                af[mi][2] = __float_as_uint(As[(base + gid) * 36 + k + tq + 4]);
                af[mi][3] = __float_as_uint(As[(base + gid + 8) * 36 + k + tq + 4]);
            }
            uint32_t bf[8][2];
#pragma unroll
            for (int ni = 0; ni < 8; ni++) {
                int n = wn + ni * 8 + gid;
                bf[ni][0] = __float_as_uint(Bs[(k + tq) * 136 + n]);
                bf[ni][1] = __float_as_uint(Bs[(k + tq + 4) * 136 + n]);
            }
#pragma unroll
            for (int mi = 0; mi < 2; mi++)
#pragma unroll
                for (int ni = 0; ni < 8; ni++)
                    mma_tf32(acc[mi][ni], af[mi], bf[ni]);
        }
        __syncthreads();
    }

    const int ncol0 = nt * 128;
    float rs[2][2] = {}, rq[2][2] = {};
#pragma unroll
    for (int mi = 0; mi < 2; mi++)
#pragma unroll
        for (int ni = 0; ni < 8; ni++) {
            int r0 = m0 + wm + mi * 16 + gid;
            int cc = ncol0 + wn + ni * 8 + tq * 2;
            float* c = acc[mi][ni];
            float2 bv = *reinterpret_cast<const float2*>(&bias[cc]);
            float2 x0 = *reinterpret_cast<const float2*>(&g_xr[(size_t)r0 * CC + cc]);
            float2 x1 = *reinterpret_cast<const float2*>(&g_xr[(size_t)(r0 + 8) * CC + cc]);
            float y0x = c[0] + bv.x + x0.x, y0y = c[1] + bv.y + x0.y;
            float y1x = c[2] + bv.x + x1.x, y1y = c[3] + bv.y + x1.y;
            *reinterpret_cast<float2*>(&g_y[(size_t)r0 * CC + cc]) = make_float2(y0x, y0y);
            *reinterpret_cast<float2*>(&g_y[(size_t)(r0 + 8) * CC + cc]) = make_float2(y1x, y1y);
            rs[mi][0] += y0x + y0y; rq[mi][0] = fmaf(y0x, y0x, fmaf(y0y, y0y, rq[mi][0]));
            rs[mi][1] += y1x + y1y; rq[mi][1] = fmaf(y1x, y1x, fmaf(y1y, y1y, rq[mi][1]));
        }
#pragma unroll
    for (int o = 1; o <= 2; o <<= 1)
#pragma unroll
        for (int mi = 0; mi < 2; mi++)
#pragma unroll
            for (int h = 0; h < 2; h++) {
                rs[mi][h] += __shfl_xor_sync(~0u, rs[mi][h], o);
                rq[mi][h] += __shfl_xor_sync(~0u, rq[mi][h], o);
            }
    if (tq == 0) {
#pragma unroll
        for (int mi = 0; mi < 2; mi++)
#pragma unroll
            for (int h = 0; h < 2; h++) {
                int rl = wm + mi * 16 + gid + h * 8;
                lsum[rl][warp & 1] = rs[mi][h];
                lsq [rl][warp & 1] = rq[mi][h];
            }
    }
    __syncthreads();
    if (tid < 128) {
        float s = lsum[tid][0] + lsum[tid][1];
        float q = lsq [tid][0] + lsq [tid][1];
        g_lnp[(size_t)(m0 + tid) * 4 + nt] = make_float2(s, q);
    }
}

// -------- finalize LN stats --------
__global__ void ln_fin_kernel() {
    int row = blockIdx.x * 256 + threadIdx.x;
    if (row >= NROWS) return;
    const float2* p = g_lnp + (size_t)row * 4;
    float s = 0.f, q = 0.f;
#pragma unroll
    for (int i = 0; i < 4; i++) { float2 v = p[i]; s += v.x; q += v.y; }
    float mu = s * (1.f / CC);
    float var = q * (1.f / CC) - mu * mu;
    g_stats[row] = make_float2(mu, rsqrtf(var + 1e-5f));
}

// -------- apply LN + transpose back to [B,T,C,HW] --------
__global__ void transpose_out_kernel(const float* __restrict__ ln_g,
                                     const float* __restrict__ ln_b,
                                     float* __restrict__ out) {
    __shared__ float tile[32][33];
    int bt = blockIdx.z;
    int n0 = blockIdx.x * 32;
    int c0 = blockIdx.y * 32;
    int tx = threadIdx.x, ty = threadIdx.y;
    int b = bt >> 6, t = bt & 63;
    float lg = ln_g[c0 + tx], lb = ln_b[c0 + tx];
#pragma unroll
    for (int i = 0; i < 4; i++) {
        int nl = ty + i * 8;
        int n = n0 + nl;
        if (n < HW) {
            int bn = b * HW + n;
            float2 st = g_stats[bn * TT + t];
            float v = g_y[(((size_t)bn) * TT + t) * CC + c0 + tx];
            tile[nl][tx] = (v - st.x) * st.y * lg + lb;
        }
    }
    __syncthreads();
#pragma unroll
    for (int i = 0; i < 4; i++) {
        int cl = ty + i * 8;
        int n = n0 + tx;
        if (n < HW)
            out[((size_t)bt * CC + (c0 + cl)) * HW + n] = tile[tx][cl];
    }
}

extern "C" void kernel_launch(void* const* d_in, const int* in_sizes, int n_in,
                              void* d_out, int out_size) {
    const float* x    = (const float*)d_in[0];
    const float* Wg   = (const float*)d_in[1];
    const float* a1   = (const float*)d_in[2];
    const float* a2   = (const float*)d_in[3];
    const float* W2   = (const float*)d_in[4];
    const float* b2   = (const float*)d_in[5];
    const float* ln_g = (const float*)d_in[6];
    const float* ln_b = (const float*)d_in[7];
    float* out = (float*)d_out;

    cudaFuncSetAttribute(gat_fused_kernel,
                         cudaFuncAttributeMaxDynamicSharedMemorySize, GAT_SMEM);
    cudaFuncSetAttribute(gemm_out_kernel,
                         cudaFuncAttributeMaxDynamicSharedMemorySize, GEMM1_SMEM);

    transpose_in_kernel<<<dim3(7, 16, BB * TT), dim3(32, 8)>>>(x);
    sel2_kernel<<<BN, 64>>>();
    gat_fused_kernel<<<dim3(NROWS / 128, 4), 512, GAT_SMEM>>>(Wg, a1, a2, out);
    gemm_out_kernel<<<dim3(NROWS / 128, 4), 256, GEMM1_SMEM>>>(out, W2, b2);
    ln_fin_kernel<<<(NROWS + 255) / 256, 256>>>();
    transpose_out_kernel<<<dim3(7, 16, BB * TT), dim3(32, 8)>>>(ln_g, ln_b, out);
}